// round 14
// baseline (speedup 1.0000x reference)
#include <cuda_runtime.h>
#include <cuda_bf16.h>

#define B_TOTAL 32768
#define HID 128
#define NC  10
#define G   2
#define THREADS 128
#define QP  144                  // q/k/v row stride (floats); head h at 36h
#define GFLN 6912                // per-graph floats: q|k|v, 3*16*144

// byte layout (per CTA, 112224 B total)
#define BUF_HI 0u                // 18432 B B-tile khalf hi
#define BUF_LO 18432u            // 18432 B B-tile khalf lo
#define AB     36864u            // A-mirror: 32 rows x 272 B (hi), then lo
#define A_LOF  8704u             // lo plane offset within A region
#define DATA_F 13568             // float idx of qkv data (byte 54272)
#define BIAS_F 27392             // float idx (byte 109568)
#define MB0    112208u
#define MB1    112216u
#define SMEM_BYTES 112224

// smem bias layout (floats)
#define SB_LNG 0
#define SB_LNB 256
#define SB_B1  512
#define SB_B2  640

// g_wpre layout: 7 projections x 73728 (kh0_hi|kh0_lo|kh1_hi|kh1_lo, 18432 each),
// then 8 W1T chunks x 18432
#define PROJ_B  73728
#define W1T_OFF 516096
__device__ __align__(16) unsigned char g_wpre[663552];

static __device__ __forceinline__ unsigned su32(const void* p) {
    return (unsigned)__cvta_generic_to_shared(p);
}
static __device__ __forceinline__ void mbar_init(unsigned a, unsigned c) {
    asm volatile("mbarrier.init.shared.b64 [%0], %1;" :: "r"(a), "r"(c) : "memory");
}
static __device__ __forceinline__ void mbw(unsigned a, unsigned par) {
    asm volatile("{\n\t.reg .pred P;\nW%=:\n\t"
        "mbarrier.try_wait.parity.acquire.cta.shared::cta.b64 P, [%0], %1, 0x989680;\n\t"
        "@!P bra W%=;\n\t}" :: "r"(a), "r"(par) : "memory");
}
static __device__ __forceinline__ void bulk_issue(unsigned dst, const void* src,
                                                  unsigned bytes, unsigned mbar) {
    asm volatile("mbarrier.arrive.expect_tx.shared::cta.b64 _, [%0], %1;"
                 :: "r"(mbar), "r"(bytes) : "memory");
    asm volatile("cp.async.bulk.shared::cluster.global.mbarrier::complete_tx::bytes "
                 "[%0], [%1], %2, [%3];" :: "r"(dst), "l"(src), "r"(bytes), "r"(mbar)
                 : "memory");
}

#define LDSM4(r0,r1,r2,r3,adr) asm volatile( \
    "ldmatrix.sync.aligned.m8n8.x4.shared.b16 {%0,%1,%2,%3}, [%4];" \
    : "=r"(r0), "=r"(r1), "=r"(r2), "=r"(r3) : "r"(adr))

#define MMA4(acp,a,b0,b1) asm volatile( \
    "mma.sync.aligned.m16n8k16.row.col.f32.bf16.bf16.f32 " \
    "{%0,%1,%2,%3}, {%4,%5,%6,%7}, {%8,%9}, {%0,%1,%2,%3};" \
    : "+f"((acp)[0]), "+f"((acp)[1]), "+f"((acp)[2]), "+f"((acp)[3]) \
    : "r"((a)[0]), "r"((a)[1]), "r"((a)[2]), "r"((a)[3]), "r"(b0), "r"(b1))

static __device__ __forceinline__ void split2(float2 f, unsigned& hi, unsigned& lo) {
    asm("cvt.rn.bf16x2.f32 %0, %1, %2;" : "=r"(hi) : "f"(f.y), "f"(f.x));
    float lx = f.x - __uint_as_float(hi << 16);
    float ly = f.y - __uint_as_float(hi & 0xffff0000u);
    asm("cvt.rn.bf16x2.f32 %0, %1, %2;" : "=r"(lo) : "f"(ly), "f"(lx));
}
static __device__ __forceinline__ float blo(unsigned v) { return __uint_as_float(v << 16); }
static __device__ __forceinline__ float bhi(unsigned v) { return __uint_as_float(v & 0xffff0000u); }

// ---------- prep: B khalf tiles (stride-144 rows) + W1T 32-k chunks ----------
__global__ void prep_kernel(const float* __restrict__ encW, const float* __restrict__ Wq,
                            const float* __restrict__ Wk,  const float* __restrict__ Wv,
                            const float* __restrict__ W1)
{
    int b = blockIdx.x;
    if (b < 7) {
        const float* src; int K;
        if (b == 0) { src = encW; K = 64; }
        else {
            int i = b - 1, l = i / 3, w = i % 3;
            src = (w == 0 ? Wq : w == 1 ? Wk : Wv) + l*16384; K = 128;
        }
        unsigned char* base = g_wpre + b*PROJ_B;
        int nkh = K / 64;
        for (int idx = threadIdx.x; idx < nkh*128*72; idx += blockDim.x) {
            int kh = idx / (128*72);
            int rem = idx % (128*72);
            int n = rem / 72, kk = rem % 72;
            float v = (kk < 64) ? src[(kh*64 + kk)*128 + n] : 0.f;
            __nv_bfloat16 h = __float2bfloat16(v);
            __nv_bfloat16 lo = __float2bfloat16(v - __bfloat162float(h));
            unsigned char* d = base + kh*36864 + n*144 + kk*2;
            *(__nv_bfloat16*)d           = h;
            *(__nv_bfloat16*)(d + 18432) = lo;
        }
    } else {
        int c = b - 7;      // W1T chunk 0..7 (32 k each), layout [col][36 floats]
        float* dst = (float*)(g_wpre + W1T_OFF + c*18432);
        for (int idx = threadIdx.x; idx < 128*36; idx += blockDim.x) {
            int col = idx / 36, kk = idx % 36;
            dst[col*36 + kk] = (kk < 32) ? W1[(c*32 + kk)*128 + col] : 0.f;
        }
    }
}

// fused 3-pass MMA for one khalf: A frags loaded once, B hi+lo per j.
// 2 graphs x 32 cols per warp.
static __device__ __forceinline__ void mma_kh(unsigned aB0, unsigned aB1, unsigned aoff,
                                              unsigned bHi, unsigned bLo,
                                              float* __restrict__ acc, int lane)
{
    const unsigned aLane = (unsigned)((lane & 15)*272 + (lane >> 4)*16);
    const int m = lane >> 3, r = lane & 7;
    const unsigned bLane = (unsigned)(((m >> 1)*8 + r)*144 + (m & 1)*16);
#pragma unroll
    for (int ks = 0; ks < 4; ks++) {
        unsigned a0h[4], a0l[4], a1h[4], a1l[4];
        unsigned aa0 = aB0 + aoff + ks*32 + aLane;
        unsigned aa1 = aB1 + aoff + ks*32 + aLane;
        LDSM4(a0h[0],a0h[1],a0h[2],a0h[3], aa0);
        LDSM4(a0l[0],a0l[1],a0l[2],a0l[3], aa0 + A_LOF);
        LDSM4(a1h[0],a1h[1],a1h[2],a1h[3], aa1);
        LDSM4(a1l[0],a1l[1],a1l[2],a1l[3], aa1 + A_LOF);
#pragma unroll
        for (int j = 0; j < 2; j++) {
            unsigned off = (unsigned)(j*2304 + ks*32) + bLane;
            unsigned bh0,bh1,bh2,bh3, bl0,bl1,bl2,bl3;
            LDSM4(bh0,bh1,bh2,bh3, bHi + off);
            LDSM4(bl0,bl1,bl2,bl3, bLo + off);
            float* p00 = acc + j*8;      float* p01 = acc + j*8 + 4;
            float* p10 = acc + 16 + j*8; float* p11 = acc + 16 + j*8 + 4;
            MMA4(p00, a0h, bh0, bh1); MMA4(p01, a0h, bh2, bh3);
            MMA4(p10, a1h, bh0, bh1); MMA4(p11, a1h, bh2, bh3);
            MMA4(p00, a0l, bh0, bh1); MMA4(p01, a0l, bh2, bh3);
            MMA4(p10, a1l, bh0, bh1); MMA4(p11, a1l, bh2, bh3);
            MMA4(p00, a0h, bl0, bl1); MMA4(p01, a0h, bl2, bl3);
            MMA4(p10, a1h, bl0, bl1); MMA4(p11, a1h, bl2, bl3);
        }
    }
}

static __device__ __forceinline__ void acc_init_g(float* acc, const float* __restrict__ bp,
                                                  int cq, int lane) {
    const int q2 = (lane & 3)*2;
#pragma unroll
    for (int nt = 0; nt < 4; nt++) {
        int col = 32*cq + nt*8 + q2;
        float2 bv2 = __ldg((const float2*)(bp + col));
        acc[nt*4]=bv2.x; acc[nt*4+1]=bv2.y; acc[nt*4+2]=bv2.x; acc[nt*4+3]=bv2.y;
        acc[16+nt*4]=bv2.x; acc[16+nt*4+1]=bv2.y;
        acc[16+nt*4+2]=bv2.x; acc[16+nt*4+3]=bv2.y;
    }
}

__global__ void __launch_bounds__(THREADS, 2)
gnn_mma_kernel(const float* __restrict__ x,
               const float* __restrict__ enc_b, const float* __restrict__ bq,
               const float* __restrict__ bk,    const float* __restrict__ bv,
               const float* __restrict__ ln_g,  const float* __restrict__ ln_b,
               const float* __restrict__ b1,    const float* __restrict__ W2,
               const float* __restrict__ b2,    float* __restrict__ out)
{
    extern __shared__ float sm[];
    char* smc = (char*)sm;
    const unsigned smb = su32(sm);
    float* bias  = sm + BIAS_F;
    float* dataF = sm + DATA_F;
    const int tid = threadIdx.x, lane = tid & 31, warp = tid >> 5;
    const int gs = warp >> 1, wsub = warp & 1, n0 = wsub * 8;
    const int cq = warp;                       // 4 warps = 4 col quarters
    const int gq = lane >> 2, q2 = (lane & 3)*2;

    if (tid == 0) {
        mbar_init(smb + MB0, 1); mbar_init(smb + MB1, 1);
        asm volatile("fence.proxy.async.shared::cta;" ::: "memory");
        bulk_issue(smb + BUF_HI, g_wpre,         18432u, smb + MB0);   // enc kh0 hi
        bulk_issue(smb + BUF_LO, g_wpre + 18432, 18432u, smb + MB1);   // enc kh0 lo
    }
    for (int i = tid; i < 256; i += THREADS) {
        bias[SB_LNG + i] = ln_g[i];
        bias[SB_LNB + i] = ln_b[i];
    }
    for (int i = tid; i < 128; i += THREADS) bias[SB_B1 + i] = b1[i];
    if (tid < NC) bias[SB_B2 + tid] = b2[tid];
    {   // stage x as bf16 hi/lo A-mirror (2 graphs, K=64)
        const float4* xs = (const float4*)(x + (size_t)blockIdx.x * (G*16*64));
        for (int i = tid; i < 512; i += THREADS) {
            int g = i >> 8, row = (i >> 4) & 15, kq = i & 15;
            float4 t = xs[i];
            unsigned h0,l0,h1,l1;
            split2(make_float2(t.x, t.y), h0, l0);
            split2(make_float2(t.z, t.w), h1, l1);
            unsigned off = AB + (unsigned)((g*16 + row)*272 + kq*8);
            *(unsigned*)(smc + off)            = h0;
            *(unsigned*)(smc + off + 4)        = h1;
            *(unsigned*)(smc + off + A_LOF)    = l0;
            *(unsigned*)(smc + off + A_LOF+4)  = l1;
        }
    }
    __syncthreads();

    const unsigned aB0 = smb + AB;
    const unsigned aB1 = smb + AB + 16*272;
    const unsigned bOfs = (unsigned)(cq*4608);    // 32 rows x 144 B per quarter
    float acc[32];

    // ---- encode (stage 0): h = x @ enc_W + enc_b -> A-mirror ----
    acc_init_g(acc, enc_b, cq, lane);
    mbw(smb + MB0, 0); mbw(smb + MB1, 0);
    mma_kh(aB0, aB1, 0, smb + BUF_HI + bOfs, smb + BUF_LO + bOfs, acc, lane);
    __syncthreads();
    if (tid == 0) {
        bulk_issue(smb + BUF_HI, g_wpre + PROJ_B,         18432u, smb + MB0);
        bulk_issue(smb + BUF_LO, g_wpre + PROJ_B + 18432, 18432u, smb + MB1);
    }
#pragma unroll
    for (int ga = 0; ga < 2; ga++) {
#pragma unroll
        for (int nt = 0; nt < 4; nt++) {
            int idx = ga*16 + nt*4;
            int lc  = 32*cq + nt*8 + q2;
            unsigned h0,l0,h1,l1;
            split2(make_float2(acc[idx],   acc[idx+1]), h0, l0);
            split2(make_float2(acc[idx+2], acc[idx+3]), h1, l1);
            unsigned o0 = AB + (unsigned)((ga*16 + gq)*272 + lc*2);
            *(unsigned*)(smc + o0)          = h0;
            *(unsigned*)(smc + o0 + A_LOF)  = l0;
            unsigned o1 = o0 + 8*272;
            *(unsigned*)(smc + o1)          = h1;
            *(unsigned*)(smc + o1 + A_LOF)  = l1;
        }
    }
    __syncthreads();

    const float scale = 0.1767766952966369f;
    for (int l = 0; l < 2; l++) {
        for (int s = 0; s < 3; s++) {
            const float* bp = (s == 0 ? bq : s == 1 ? bk : bv) + 128*l;
            acc_init_g(acc, bp, cq, lane);
#pragma unroll
            for (int kh = 0; kh < 2; kh++) {
                int st = 1 + l*6 + s*2 + kh;
                int nx = st + 1;
                const unsigned char* nsrc = (nx <= 12)
                    ? g_wpre + (1 + (nx - 1)/2)*PROJ_B + ((nx - 1) & 1)*36864
                    : g_wpre + W1T_OFF;
                mbw(smb + MB0, st & 1);
                mbw(smb + MB1, st & 1);
                mma_kh(aB0, aB1, (unsigned)(kh*128),
                       smb + BUF_HI + bOfs, smb + BUF_LO + bOfs, acc, lane);
                __syncthreads();
                if (tid == 0) {
                    bulk_issue(smb + BUF_HI, nsrc,         18432u, smb + MB0);
                    bulk_issue(smb + BUF_LO, nsrc + 18432, 18432u, smb + MB1);
                }
            }
            // epilogue -> q/k/v fp32 (head-padded); overlaps next TMA
#pragma unroll
            for (int ga = 0; ga < 2; ga++) {
                float* base = dataF + ga*GFLN + s*2304;
#pragma unroll
                for (int nt = 0; nt < 4; nt++) {
                    int idx = ga*16 + nt*4;
                    int off = cq*36 + nt*8 + q2;
                    *(float2*)(base + gq*QP + off)       = make_float2(acc[idx],   acc[idx+1]);
                    *(float2*)(base + (gq + 8)*QP + off) = make_float2(acc[idx+2], acc[idx+3]);
                }
            }
        }
        __syncthreads();

        // ---- attention + residual(mirror) + LN (writes new mirror) ----
        {
            float* qg = dataF + gs*GFLN;
            float* kg = qg + 2304;
            float* vg = kg + 2304;
            const int n  = n0 + (lane & 7);
            const int hh = lane >> 3;
            const int co = hh * 36, ch = hh * 32;
            float q[32];
            const float* qr = qg + n*QP + co;
#pragma unroll
            for (int j = 0; j < 8; j++) {
                float4 t = *(const float4*)(qr + 4*j);
                q[4*j] = t.x; q[4*j+1] = t.y; q[4*j+2] = t.z; q[4*j+3] = t.w;
            }
            float s[16];
#pragma unroll
            for (int m = 0; m < 16; m++) {
                const float* kr = kg + m*QP + co;
                float a0 = 0.f, a1 = 0.f, a2 = 0.f, a3 = 0.f;
#pragma unroll
                for (int j = 0; j < 8; j++) {
                    float4 t = *(const float4*)(kr + 4*j);
                    a0 += q[4*j]*t.x; a1 += q[4*j+1]*t.y;
                    a2 += q[4*j+2]*t.z; a3 += q[4*j+3]*t.w;
                }
                s[m] = (a0 + a1 + a2 + a3) * scale;
            }
            float mx = s[0];
#pragma unroll
            for (int m = 1; m < 16; m++) mx = fmaxf(mx, s[m]);
            float ssum = 0.f;
#pragma unroll
            for (int m = 0; m < 16; m++) { s[m] = __expf(s[m] - mx); ssum += s[m]; }
            float inv = 1.f / ssum;
            float o[32];
#pragma unroll
            for (int j = 0; j < 32; j++) o[j] = 0.f;
#pragma unroll
            for (int m = 0; m < 16; m++) {
                float p = s[m] * inv;
                const float* vr = vg + m*QP + co;
#pragma unroll
                for (int j = 0; j < 8; j++) {
                    float4 t = *(const float4*)(vr + 4*j);
                    o[4*j] += p*t.x; o[4*j+1] += p*t.y;
                    o[4*j+2] += p*t.z; o[4*j+3] += p*t.w;
                }
            }
            char* ap = smc + AB + (unsigned)((gs*16 + n)*272 + ch*2);
#pragma unroll
            for (int u = 0; u < 4; u++) {
                uint4 H = *(const uint4*)(ap + 16*u);
                uint4 L = *(const uint4*)(ap + A_LOF + 16*u);
                o[8*u]   += blo(H.x) + blo(L.x);  o[8*u+1] += bhi(H.x) + bhi(L.x);
                o[8*u+2] += blo(H.y) + blo(L.y);  o[8*u+3] += bhi(H.y) + bhi(L.y);
                o[8*u+4] += blo(H.z) + blo(L.z);  o[8*u+5] += bhi(H.z) + bhi(L.z);
                o[8*u+6] += blo(H.w) + blo(L.w);  o[8*u+7] += bhi(H.w) + bhi(L.w);
            }
            float lsum = 0.f, lsq = 0.f;
#pragma unroll
            for (int j = 0; j < 32; j++) { lsum += o[j]; lsq += o[j]*o[j]; }
            lsum += __shfl_xor_sync(0xffffffffu, lsum, 8);
            lsq  += __shfl_xor_sync(0xffffffffu, lsq,  8);
            lsum += __shfl_xor_sync(0xffffffffu, lsum, 16);
            lsq  += __shfl_xor_sync(0xffffffffu, lsq,  16);
            float mean = lsum * (1.f/HID);
            float var  = lsq  * (1.f/HID) - mean*mean;
            float rstd = rsqrtf(var + 1e-5f);
#pragma unroll
            for (int j = 0; j < 32; j++)
                o[j] = (o[j] - mean)*rstd*bias[SB_LNG + 128*l + ch + j]
                       + bias[SB_LNB + 128*l + ch + j];
#pragma unroll
            for (int u = 0; u < 4; u++) {
                unsigned hh4[4], ll4[4];
#pragma unroll
                for (int e = 0; e < 4; e++)
                    split2(make_float2(o[8*u + 2*e], o[8*u + 2*e + 1]), hh4[e], ll4[e]);
                *(uint4*)(ap + 16*u)          = make_uint4(hh4[0], hh4[1], hh4[2], hh4[3]);
                *(uint4*)(ap + A_LOF + 16*u)  = make_uint4(ll4[0], ll4[1], ll4[2], ll4[3]);
            }
        }
        __syncthreads();
    }

    {   // pooling from mirror -> scr (mean[0..127] | max[128..255]) per graph
        int cp = wsub*64 + 2*lane;
        const char* ap = smc + AB + (unsigned)((gs*16)*272 + cp*2);
        float s0 = 0.f, s1 = 0.f, m0 = -3.4e38f, m1 = -3.4e38f;
#pragma unroll
        for (int nn = 0; nn < 16; nn++) {
            unsigned H = *(const unsigned*)(ap + nn*272);
            unsigned L = *(const unsigned*)(ap + nn*272 + A_LOF);
            float h0 = blo(H) + blo(L), h1 = bhi(H) + bhi(L);
            s0 += h0; m0 = fmaxf(m0, h0);
            s1 += h1; m1 = fmaxf(m1, h1);
        }
        float* scr = dataF + gs*GFLN;
        *(float2*)(scr + cp)       = make_float2(s0*(1.f/16.f), s1*(1.f/16.f));
        *(float2*)(scr + 128 + cp) = make_float2(m0, m1);
    }
    __syncthreads();

    // ---- MLP layer 1: W1T in 8 32-k chunks ping-ponged through hi/lo bufs ----
    int mb0u = 13, mb1u = 13;      // mbar completion counts so far
    {
        int g2 = lane >> 4, c16 = lane & 15;
        int c = warp*32 + c16;
        float a1 = bias[SB_B1 + c], a2 = bias[SB_B1 + c + 16];
        const float* pooled = dataF + g2*GFLN;
        for (int ch = 0; ch < 8; ch++) {
            unsigned mb = (ch & 1) ? MB1 : MB0;
            int par = ((ch & 1) ? mb1u++ : mb0u++) & 1;
            mbw(smb + mb, par);
            const float* Wc = (const float*)(smc + ((ch & 1) ? BUF_LO : BUF_HI));
#pragma unroll
            for (int k4 = 0; k4 < 8; k4++) {
                float4 p = *(const float4*)(pooled + ch*32 + 4*k4);
                float4 w = *(const float4*)(Wc + c*36 + 4*k4);
                float4 v = *(const float4*)(Wc + (c + 16)*36 + 4*k4);
                a1 = fmaf(p.x, w.x, fmaf(p.y, w.y, fmaf(p.z, w.z, fmaf(p.w, w.w, a1))));
                a2 = fmaf(p.x, v.x, fmaf(p.y, v.y, fmaf(p.z, v.z, fmaf(p.w, v.w, a2))));
            }
            __syncthreads();
            if (tid == 0) {
                if (ch + 2 <= 7)
                    bulk_issue(smb + ((ch & 1) ? BUF_LO : BUF_HI),
                               g_wpre + W1T_OFF + (ch + 2)*18432, 18432u, smb + mb);
                else if (ch == 6)
                    bulk_issue(smb + BUF_HI, W2, 5120u, smb + MB0);
            }
        }
        float* hid = dataF + g2*GFLN + 256;
        hid[c]      = fmaxf(a1, 0.f);
        hid[c + 16] = fmaxf(a2, 0.f);
    }
    __syncthreads();

    // ---- logits = hid @ W2 + b2 ----
    mbw(smb + MB0, mb0u & 1);                 // W2 = MB0 completion #17 -> parity 1
    {
        const float* Wc = (const float*)(smc + BUF_HI);
        if (wsub == 0 && lane < NC) {
            const float* hid = dataF + gs*GFLN + 256;
            float a = bias[SB_B2 + lane];
#pragma unroll 8
            for (int k = 0; k < HID; k++)
                a = fmaf(hid[k], Wc[k*NC + lane], a);
            out[((size_t)blockIdx.x*G + gs)*NC + lane] = a;
        }
    }
}

extern "C" void kernel_launch(void* const* d_in, const int* in_sizes, int n_in,
                              void* d_out, int out_size)
{
    const float* x     = (const float*)d_in[0];
    const float* enc_W = (const float*)d_in[1];
    const float* enc_b = (const float*)d_in[2];
    const float* Wq    = (const float*)d_in[3];
    const float* bq    = (const float*)d_in[4];
    const float* Wk    = (const float*)d_in[5];
    const float* bk    = (const float*)d_in[6];
    const float* Wv    = (const float*)d_in[7];
    const float* bv    = (const float*)d_in[8];
    const float* ln_g  = (const float*)d_in[9];
    const float* ln_b  = (const float*)d_in[10];
    const float* W1    = (const float*)d_in[11];
    const float* b1    = (const float*)d_in[12];
    const float* W2    = (const float*)d_in[13];
    const float* b2    = (const float*)d_in[14];
    float* out = (float*)d_out;

    prep_kernel<<<15, 256>>>(enc_W, Wq, Wk, Wv, W1);
    cudaFuncSetAttribute(gnn_mma_kernel,
                         cudaFuncAttributeMaxDynamicSharedMemorySize, SMEM_BYTES);
    gnn_mma_kernel<<<B_TOTAL / G, THREADS, SMEM_BYTES>>>(
        x, enc_b, bq, bk, bv, ln_g, ln_b, b1, W2, b2, out);
}

// round 16
// speedup vs baseline: 1.2056x; 1.2056x over previous
#include <cuda_runtime.h>
#include <cuda_fp16.h>

#define B_TOTAL 32768
#define HID 128
#define NC  10
#define G   2
#define THREADS 128
#define QP  144                  // q/k/v row stride (floats); head h at 36h
#define GFLN 6912                // per-graph floats: q|k|v, 3*16*144

// byte layout (per CTA, 103504 B total)
#define BUF_HI 0u                // 18432 B B-tile khalf hi
#define BUF_LO 18432u            // 18432 B B-tile khalf lo
#define AB     36864u            // A-mirror: 32 rows x 272 B (fp16, single plane)
#define DATA_F 11392             // float idx of qkv data (byte 45568)
#define BIAS_F 25216             // float idx (byte 100864)
#define MB0    103488u
#define MB1    103496u
#define SMEM_BYTES 103504

// smem bias layout (floats)
#define SB_LNG 0
#define SB_LNB 256
#define SB_B1  512
#define SB_B2  640

// g_wpre layout: 7 projections x 73728 (kh0_hi|kh0_lo|kh1_hi|kh1_lo, 18432 each),
// then 8 W1T chunks x 18432
#define PROJ_B  73728
#define W1T_OFF 516096
__device__ __align__(16) unsigned char g_wpre[663552];

static __device__ __forceinline__ unsigned su32(const void* p) {
    return (unsigned)__cvta_generic_to_shared(p);
}
static __device__ __forceinline__ void mbar_init(unsigned a, unsigned c) {
    asm volatile("mbarrier.init.shared.b64 [%0], %1;" :: "r"(a), "r"(c) : "memory");
}
static __device__ __forceinline__ void mbw(unsigned a, unsigned par) {
    asm volatile("{\n\t.reg .pred P;\nW%=:\n\t"
        "mbarrier.try_wait.parity.acquire.cta.shared::cta.b64 P, [%0], %1, 0x989680;\n\t"
        "@!P bra W%=;\n\t}" :: "r"(a), "r"(par) : "memory");
}
static __device__ __forceinline__ void bulk_issue(unsigned dst, const void* src,
                                                  unsigned bytes, unsigned mbar) {
    asm volatile("mbarrier.arrive.expect_tx.shared::cta.b64 _, [%0], %1;"
                 :: "r"(mbar), "r"(bytes) : "memory");
    asm volatile("cp.async.bulk.shared::cluster.global.mbarrier::complete_tx::bytes "
                 "[%0], [%1], %2, [%3];" :: "r"(dst), "l"(src), "r"(bytes), "r"(mbar)
                 : "memory");
}

#define LDSM4(r0,r1,r2,r3,adr) asm volatile( \
    "ldmatrix.sync.aligned.m8n8.x4.shared.b16 {%0,%1,%2,%3}, [%4];" \
    : "=r"(r0), "=r"(r1), "=r"(r2), "=r"(r3) : "r"(adr))

#define MMA4(acp,a,b0,b1) asm volatile( \
    "mma.sync.aligned.m16n8k16.row.col.f32.f16.f16.f32 " \
    "{%0,%1,%2,%3}, {%4,%5,%6,%7}, {%8,%9}, {%0,%1,%2,%3};" \
    : "+f"((acp)[0]), "+f"((acp)[1]), "+f"((acp)[2]), "+f"((acp)[3]) \
    : "r"((a)[0]), "r"((a)[1]), "r"((a)[2]), "r"((a)[3]), "r"(b0), "r"(b1))

// pack two fp32 -> f16x2 (lo lane = first arg)
static __device__ __forceinline__ unsigned packh2(float x, float y) {
    unsigned r;
    asm("cvt.rn.f16x2.f32 %0, %1, %2;" : "=r"(r) : "f"(y), "f"(x));
    return r;
}
static __device__ __forceinline__ float hlo(unsigned v) {
    __half2 h = *reinterpret_cast<__half2*>(&v);
    return __low2float(h);
}
static __device__ __forceinline__ float hhi(unsigned v) {
    __half2 h = *reinterpret_cast<__half2*>(&v);
    return __high2float(h);
}

// ---------- prep: fp16 hi/lo B khalf tiles (stride-144 rows) + W1T chunks ----------
__global__ void prep_kernel(const float* __restrict__ encW, const float* __restrict__ Wq,
                            const float* __restrict__ Wk,  const float* __restrict__ Wv,
                            const float* __restrict__ W1)
{
    int b = blockIdx.x;
    if (b < 7) {
        const float* src; int K;
        if (b == 0) { src = encW; K = 64; }
        else {
            int i = b - 1, l = i / 3, w = i % 3;
            src = (w == 0 ? Wq : w == 1 ? Wk : Wv) + l*16384; K = 128;
        }
        unsigned char* base = g_wpre + b*PROJ_B;
        int nkh = K / 64;
        for (int idx = threadIdx.x; idx < nkh*128*72; idx += blockDim.x) {
            int kh = idx / (128*72);
            int rem = idx % (128*72);
            int n = rem / 72, kk = rem % 72;
            float v = (kk < 64) ? src[(kh*64 + kk)*128 + n] : 0.f;
            __half h = __float2half(v);
            __half lo = __float2half(v - __half2float(h));
            unsigned char* d = base + kh*36864 + n*144 + kk*2;
            *(__half*)d           = h;
            *(__half*)(d + 18432) = lo;
        }
    } else {
        int c = b - 7;      // W1T chunk 0..7 (32 k each), layout [col][36 floats]
        float* dst = (float*)(g_wpre + W1T_OFF + c*18432);
        for (int idx = threadIdx.x; idx < 128*36; idx += blockDim.x) {
            int col = idx / 36, kk = idx % 36;
            dst[col*36 + kk] = (kk < 32) ? W1[(c*32 + kk)*128 + col] : 0.f;
        }
    }
}

// one B-pass MMA for one khalf (used for both B_hi and B_lo passes).
// 2 graphs x 32 cols per warp; A is single fp16 plane.
static __device__ __forceinline__ void mma_pass(unsigned aB0, unsigned aB1, unsigned aoff,
                                                unsigned bBase, float* __restrict__ acc,
                                                int lane)
{
    const unsigned aLane = (unsigned)((lane & 15)*272 + (lane >> 4)*16);
    const int m = lane >> 3, r = lane & 7;
    const unsigned bLane = (unsigned)(((m >> 1)*8 + r)*144 + (m & 1)*16);
#pragma unroll
    for (int ks = 0; ks < 4; ks++) {
        unsigned a0[4], a1[4];
        LDSM4(a0[0],a0[1],a0[2],a0[3], aB0 + aoff + ks*32 + aLane);
        LDSM4(a1[0],a1[1],a1[2],a1[3], aB1 + aoff + ks*32 + aLane);
#pragma unroll
        for (int j = 0; j < 2; j++) {
            unsigned ab = bBase + (unsigned)(j*2304 + ks*32) + bLane;
            unsigned b0,b1,b2,b3;
            LDSM4(b0,b1,b2,b3, ab);
            float* p00 = acc + j*8;      float* p01 = acc + j*8 + 4;
            float* p10 = acc + 16 + j*8; float* p11 = acc + 16 + j*8 + 4;
            MMA4(p00, a0, b0, b1); MMA4(p01, a0, b2, b3);
            MMA4(p10, a1, b0, b1); MMA4(p11, a1, b2, b3);
        }
    }
}

static __device__ __forceinline__ void acc_init_g(float* acc, const float* __restrict__ bp,
                                                  int cq, int lane) {
    const int q2 = (lane & 3)*2;
#pragma unroll
    for (int nt = 0; nt < 4; nt++) {
        int col = 32*cq + nt*8 + q2;
        float2 bv2 = __ldg((const float2*)(bp + col));
        acc[nt*4]=bv2.x; acc[nt*4+1]=bv2.y; acc[nt*4+2]=bv2.x; acc[nt*4+3]=bv2.y;
        acc[16+nt*4]=bv2.x; acc[16+nt*4+1]=bv2.y;
        acc[16+nt*4+2]=bv2.x; acc[16+nt*4+3]=bv2.y;
    }
}

__global__ void __launch_bounds__(THREADS, 2)
gnn_mma_kernel(const float* __restrict__ x,
               const float* __restrict__ enc_b, const float* __restrict__ bq,
               const float* __restrict__ bk,    const float* __restrict__ bv,
               const float* __restrict__ ln_g,  const float* __restrict__ ln_b,
               const float* __restrict__ b1,    const float* __restrict__ W2,
               const float* __restrict__ b2,    float* __restrict__ out)
{
    extern __shared__ float sm[];
    char* smc = (char*)sm;
    const unsigned smb = su32(sm);
    float* bias  = sm + BIAS_F;
    float* dataF = sm + DATA_F;
    const int tid = threadIdx.x, lane = tid & 31, warp = tid >> 5;
    const int gs = warp >> 1, wsub = warp & 1, n0 = wsub * 8;
    const int cq = warp;                       // 4 warps = 4 col quarters
    const int gq = lane >> 2, q2 = (lane & 3)*2;

    if (tid == 0) {
        mbar_init(smb + MB0, 1); mbar_init(smb + MB1, 1);
        asm volatile("fence.proxy.async.shared::cta;" ::: "memory");
        bulk_issue(smb + BUF_HI, g_wpre,         18432u, smb + MB0);   // enc kh0 hi
        bulk_issue(smb + BUF_LO, g_wpre + 18432, 18432u, smb + MB1);   // enc kh0 lo
    }
    for (int i = tid; i < 256; i += THREADS) {
        bias[SB_LNG + i] = ln_g[i];
        bias[SB_LNB + i] = ln_b[i];
    }
    for (int i = tid; i < 128; i += THREADS) bias[SB_B1 + i] = b1[i];
    if (tid < NC) bias[SB_B2 + tid] = b2[tid];
    {   // stage x as fp16 A-mirror (2 graphs, K=64)
        const float4* xs = (const float4*)(x + (size_t)blockIdx.x * (G*16*64));
        for (int i = tid; i < 512; i += THREADS) {
            int g = i >> 8, row = (i >> 4) & 15, kq = i & 15;
            float4 t = xs[i];
            unsigned off = AB + (unsigned)((g*16 + row)*272 + kq*8);
            *(unsigned*)(smc + off)     = packh2(t.x, t.y);
            *(unsigned*)(smc + off + 4) = packh2(t.z, t.w);
        }
    }
    __syncthreads();

    const unsigned aB0 = smb + AB;
    const unsigned aB1 = smb + AB + 16*272;
    const unsigned bOfs = (unsigned)(cq*4608);    // 32 rows x 144 B per quarter
    float acc[32];

    // ---- encode (stage 0): h = x @ enc_W + enc_b -> A-mirror ----
    acc_init_g(acc, enc_b, cq, lane);
    mbw(smb + MB0, 0);
    mma_pass(aB0, aB1, 0, smb + BUF_HI + bOfs, acc, lane);
    __syncthreads();
    if (tid == 0) bulk_issue(smb + BUF_HI, g_wpre + PROJ_B, 18432u, smb + MB0);
    mbw(smb + MB1, 0);
    mma_pass(aB0, aB1, 0, smb + BUF_LO + bOfs, acc, lane);
    __syncthreads();
    if (tid == 0) bulk_issue(smb + BUF_LO, g_wpre + PROJ_B + 18432, 18432u, smb + MB1);
#pragma unroll
    for (int ga = 0; ga < 2; ga++) {
#pragma unroll
        for (int nt = 0; nt < 4; nt++) {
            int idx = ga*16 + nt*4;
            int lc  = 32*cq + nt*8 + q2;
            unsigned o0 = AB + (unsigned)((ga*16 + gq)*272 + lc*2);
            *(unsigned*)(smc + o0)           = packh2(acc[idx],   acc[idx+1]);
            *(unsigned*)(smc + o0 + 8*272)   = packh2(acc[idx+2], acc[idx+3]);
        }
    }
    __syncthreads();

    const float scale = 0.1767766952966369f;
    for (int l = 0; l < 2; l++) {
        for (int s = 0; s < 3; s++) {
            const float* bp = (s == 0 ? bq : s == 1 ? bk : bv) + 128*l;
            acc_init_g(acc, bp, cq, lane);
#pragma unroll
            for (int kh = 0; kh < 2; kh++) {
                int st = 1 + l*6 + s*2 + kh;
                int nx = st + 1;
                const unsigned char* nsrc = (nx <= 12)
                    ? g_wpre + (1 + (nx - 1)/2)*PROJ_B + ((nx - 1) & 1)*36864
                    : g_wpre + W1T_OFF;
                mbw(smb + MB0, st & 1);
                mma_pass(aB0, aB1, (unsigned)(kh*128), smb + BUF_HI + bOfs, acc, lane);
                __syncthreads();
                if (tid == 0) bulk_issue(smb + BUF_HI, nsrc, 18432u, smb + MB0);
                mbw(smb + MB1, st & 1);
                mma_pass(aB0, aB1, (unsigned)(kh*128), smb + BUF_LO + bOfs, acc, lane);
                __syncthreads();
                if (tid == 0) bulk_issue(smb + BUF_LO, nsrc + 18432, 18432u, smb + MB1);
            }
            // epilogue -> q/k/v fp32 (head-padded); overlaps next TMA
#pragma unroll
            for (int ga = 0; ga < 2; ga++) {
                float* base = dataF + ga*GFLN + s*2304;
#pragma unroll
                for (int nt = 0; nt < 4; nt++) {
                    int idx = ga*16 + nt*4;
                    int off = cq*36 + nt*8 + q2;
                    *(float2*)(base + gq*QP + off)       = make_float2(acc[idx],   acc[idx+1]);
                    *(float2*)(base + (gq + 8)*QP + off) = make_float2(acc[idx+2], acc[idx+3]);
                }
            }
        }
        __syncthreads();

        // ---- attention + residual(mirror) + LN (writes new mirror) ----
        {
            float* qg = dataF + gs*GFLN;
            float* kg = qg + 2304;
            float* vg = kg + 2304;
            const int n  = n0 + (lane & 7);
            const int hh = lane >> 3;
            const int co = hh * 36, ch = hh * 32;
            float q[32];
            const float* qr = qg + n*QP + co;
#pragma unroll
            for (int j = 0; j < 8; j++) {
                float4 t = *(const float4*)(qr + 4*j);
                q[4*j] = t.x; q[4*j+1] = t.y; q[4*j+2] = t.z; q[4*j+3] = t.w;
            }
            float s[16];
#pragma unroll
            for (int m = 0; m < 16; m++) {
                const float* kr = kg + m*QP + co;
                float a0 = 0.f, a1 = 0.f, a2 = 0.f, a3 = 0.f;
#pragma unroll
                for (int j = 0; j < 8; j++) {
                    float4 t = *(const float4*)(kr + 4*j);
                    a0 += q[4*j]*t.x; a1 += q[4*j+1]*t.y;
                    a2 += q[4*j+2]*t.z; a3 += q[4*j+3]*t.w;
                }
                s[m] = (a0 + a1 + a2 + a3) * scale;
            }
            float mx = s[0];
#pragma unroll
            for (int m = 1; m < 16; m++) mx = fmaxf(mx, s[m]);
            float ssum = 0.f;
#pragma unroll
            for (int m = 0; m < 16; m++) { s[m] = __expf(s[m] - mx); ssum += s[m]; }
            float inv = 1.f / ssum;
            float o[32];
#pragma unroll
            for (int j = 0; j < 32; j++) o[j] = 0.f;
#pragma unroll
            for (int m = 0; m < 16; m++) {
                float p = s[m] * inv;
                const float* vr = vg + m*QP + co;
#pragma unroll
                for (int j = 0; j < 8; j++) {
                    float4 t = *(const float4*)(vr + 4*j);
                    o[4*j] += p*t.x; o[4*j+1] += p*t.y;
                    o[4*j+2] += p*t.z; o[4*j+3] += p*t.w;
                }
            }
            // residual from fp16 mirror (contiguous: uint4 u -> values 8u..8u+7)
            char* ap = smc + AB + (unsigned)((gs*16 + n)*272 + ch*2);
#pragma unroll
            for (int u = 0; u < 4; u++) {
                uint4 H = *(const uint4*)(ap + 16*u);
                o[8*u]   += hlo(H.x);  o[8*u+1] += hhi(H.x);
                o[8*u+2] += hlo(H.y);  o[8*u+3] += hhi(H.y);
                o[8*u+4] += hlo(H.z);  o[8*u+5] += hhi(H.z);
                o[8*u+6] += hlo(H.w);  o[8*u+7] += hhi(H.w);
            }
            float lsum = 0.f, lsq = 0.f;
#pragma unroll
            for (int j = 0; j < 32; j++) { lsum += o[j]; lsq += o[j]*o[j]; }
            lsum += __shfl_xor_sync(0xffffffffu, lsum, 8);
            lsq  += __shfl_xor_sync(0xffffffffu, lsq,  8);
            lsum += __shfl_xor_sync(0xffffffffu, lsum, 16);
            lsq  += __shfl_xor_sync(0xffffffffu, lsq,  16);
            float mean = lsum * (1.f/HID);
            float var  = lsq  * (1.f/HID) - mean*mean;
            float rstd = rsqrtf(var + 1e-5f);
#pragma unroll
            for (int j = 0; j < 32; j++)
                o[j] = (o[j] - mean)*rstd*bias[SB_LNG + 128*l + ch + j]
                       + bias[SB_LNB + 128*l + ch + j];
            // write new h mirror (fp16)
#pragma unroll
            for (int u = 0; u < 4; u++) {
                uint4 w4;
                w4.x = packh2(o[8*u],     o[8*u + 1]);
                w4.y = packh2(o[8*u + 2], o[8*u + 3]);
                w4.z = packh2(o[8*u + 4], o[8*u + 5]);
                w4.w = packh2(o[8*u + 6], o[8*u + 7]);
                *(uint4*)(ap + 16*u) = w4;
            }
        }
        __syncthreads();
    }

    {   // pooling from mirror -> scr (mean[0..127] | max[128..255]) per graph
        int cp = wsub*64 + 2*lane;
        const char* ap = smc + AB + (unsigned)((gs*16)*272 + cp*2);
        float s0 = 0.f, s1 = 0.f, m0 = -3.4e38f, m1 = -3.4e38f;
#pragma unroll
        for (int nn = 0; nn < 16; nn++) {
            unsigned H = *(const unsigned*)(ap + nn*272);
            float h0 = hlo(H), h1 = hhi(H);
            s0 += h0; m0 = fmaxf(m0, h0);
            s1 += h1; m1 = fmaxf(m1, h1);
        }
        float* scr = dataF + gs*GFLN;
        *(float2*)(scr + cp)       = make_float2(s0*(1.f/16.f), s1*(1.f/16.f));
        *(float2*)(scr + 128 + cp) = make_float2(m0, m1);
    }
    __syncthreads();

    // ---- MLP layer 1: W1T in 8 32-k chunks ping-ponged through hi/lo bufs ----
    int mb0u = 13, mb1u = 13;      // mbar completion counts so far
    {
        int g2 = lane >> 4, c16 = lane & 15;
        int c = warp*32 + c16;
        float a1 = bias[SB_B1 + c], a2 = bias[SB_B1 + c + 16];
        const float* pooled = dataF + g2*GFLN;
        for (int ch = 0; ch < 8; ch++) {
            unsigned mb = (ch & 1) ? MB1 : MB0;
            int par = ((ch & 1) ? mb1u++ : mb0u++) & 1;
            mbw(smb + mb, par);
            const float* Wc = (const float*)(smc + ((ch & 1) ? BUF_LO : BUF_HI));
#pragma unroll
            for (int k4 = 0; k4 < 8; k4++) {
                float4 p = *(const float4*)(pooled + ch*32 + 4*k4);
                float4 w = *(const float4*)(Wc + c*36 + 4*k4);
                float4 v = *(const float4*)(Wc + (c + 16)*36 + 4*k4);
                a1 = fmaf(p.x, w.x, fmaf(p.y, w.y, fmaf(p.z, w.z, fmaf(p.w, w.w, a1))));
                a2 = fmaf(p.x, v.x, fmaf(p.y, v.y, fmaf(p.z, v.z, fmaf(p.w, v.w, a2))));
            }
            __syncthreads();
            if (tid == 0) {
                if (ch + 2 <= 7)
                    bulk_issue(smb + ((ch & 1) ? BUF_LO : BUF_HI),
                               g_wpre + W1T_OFF + (ch + 2)*18432, 18432u, smb + mb);
                else if (ch == 6)
                    bulk_issue(smb + BUF_HI, W2, 5120u, smb + MB0);
            }
        }
        float* hid = dataF + g2*GFLN + 256;
        hid[c]      = fmaxf(a1, 0.f);
        hid[c + 16] = fmaxf(a2, 0.f);
    }
    __syncthreads();

    // ---- logits = hid @ W2 + b2 ----
    mbw(smb + MB0, mb0u & 1);                 // W2 = MB0 completion #17 -> parity 1
    {
        const float* Wc = (const float*)(smc + BUF_HI);
        if (wsub == 0 && lane < NC) {
            const float* hid = dataF + gs*GFLN + 256;
            float a = bias[SB_B2 + lane];
#pragma unroll 8
            for (int k = 0; k < HID; k++)
                a = fmaf(hid[k], Wc[k*NC + lane], a);
            out[((size_t)blockIdx.x*G + gs)*NC + lane] = a;
        }
    }
}

extern "C" void kernel_launch(void* const* d_in, const int* in_sizes, int n_in,
                              void* d_out, int out_size)
{
    const float* x     = (const float*)d_in[0];
    const float* enc_W = (const float*)d_in[1];
    const float* enc_b = (const float*)d_in[2];
    const float* Wq    = (const float*)d_in[3];
    const float* bq    = (const float*)d_in[4];
    const float* Wk    = (const float*)d_in[5];
    const float* bk    = (const float*)d_in[6];
    const float* Wv    = (const float*)d_in[7];
    const float* bv    = (const float*)d_in[8];
    const float* ln_g  = (const float*)d_in[9];
    const float* ln_b  = (const float*)d_in[10];
    const float* W1    = (const float*)d_in[11];
    const float* b1    = (const float*)d_in[12];
    const float* W2    = (const float*)d_in[13];
    const float* b2    = (const float*)d_in[14];
    float* out = (float*)d_out;

    prep_kernel<<<15, 256>>>(enc_W, Wq, Wk, Wv, W1);
    cudaFuncSetAttribute(gnn_mma_kernel,
                         cudaFuncAttributeMaxDynamicSharedMemorySize, SMEM_BYTES);
    gnn_mma_kernel<<<B_TOTAL / G, THREADS, SMEM_BYTES>>>(
        x, enc_b, bq, bk, bv, ln_g, ln_b, b1, W2, b2, out);
}

// round 17
// speedup vs baseline: 1.4858x; 1.2324x over previous
#include <cuda_runtime.h>
#include <cuda_fp16.h>

#define B_TOTAL 32768
#define HID 128
#define NC  10
#define G   2
#define THREADS 128

// byte layout (per CTA, 92752 B)
#define BUF_HI 0u
#define BUF_LO 18432u
#define AB     36864u            // A-mirror: 32 rows x 272 B fp16
#define QKV    45568u            // per graph 13056 B: Q|K|V tiles, 16x272B each
#define OSTF   17920             // float idx of O staging (byte 71680), 2304 fl/graph
#define BIAS_F 22528             // float idx (byte 90112)
#define MB0    92736u
#define MB1    92744u
#define SMEM_BYTES 92752

#define SB_LNG 0
#define SB_LNB 256
#define SB_B1  512
#define SB_B2  640

#define PROJ_B  73728
#define W1T_OFF 516096
__device__ __align__(16) unsigned char g_wpre[663552];

static __device__ __forceinline__ unsigned su32(const void* p) {
    return (unsigned)__cvta_generic_to_shared(p);
}
static __device__ __forceinline__ void mbar_init(unsigned a, unsigned c) {
    asm volatile("mbarrier.init.shared.b64 [%0], %1;" :: "r"(a), "r"(c) : "memory");
}
static __device__ __forceinline__ void mbw(unsigned a, unsigned par) {
    asm volatile("{\n\t.reg .pred P;\nW%=:\n\t"
        "mbarrier.try_wait.parity.acquire.cta.shared::cta.b64 P, [%0], %1, 0x989680;\n\t"
        "@!P bra W%=;\n\t}" :: "r"(a), "r"(par) : "memory");
}
static __device__ __forceinline__ void bulk_issue(unsigned dst, const void* src,
                                                  unsigned bytes, unsigned mbar) {
    asm volatile("mbarrier.arrive.expect_tx.shared::cta.b64 _, [%0], %1;"
                 :: "r"(mbar), "r"(bytes) : "memory");
    asm volatile("cp.async.bulk.shared::cluster.global.mbarrier::complete_tx::bytes "
                 "[%0], [%1], %2, [%3];" :: "r"(dst), "l"(src), "r"(bytes), "r"(mbar)
                 : "memory");
}

#define LDSM4(r0,r1,r2,r3,adr) asm volatile( \
    "ldmatrix.sync.aligned.m8n8.x4.shared.b16 {%0,%1,%2,%3}, [%4];" \
    : "=r"(r0), "=r"(r1), "=r"(r2), "=r"(r3) : "r"(adr))
#define LDSM4T(r0,r1,r2,r3,adr) asm volatile( \
    "ldmatrix.sync.aligned.m8n8.x4.trans.shared.b16 {%0,%1,%2,%3}, [%4];" \
    : "=r"(r0), "=r"(r1), "=r"(r2), "=r"(r3) : "r"(adr))

#define MMA4(acp,a,b0,b1) asm volatile( \
    "mma.sync.aligned.m16n8k16.row.col.f32.f16.f16.f32 " \
    "{%0,%1,%2,%3}, {%4,%5,%6,%7}, {%8,%9}, {%0,%1,%2,%3};" \
    : "+f"((acp)[0]), "+f"((acp)[1]), "+f"((acp)[2]), "+f"((acp)[3]) \
    : "r"((a)[0]), "r"((a)[1]), "r"((a)[2]), "r"((a)[3]), "r"(b0), "r"(b1))

static __device__ __forceinline__ unsigned packh2(float x, float y) {
    unsigned r;
    asm("cvt.rn.f16x2.f32 %0, %1, %2;" : "=r"(r) : "f"(y), "f"(x));
    return r;
}
static __device__ __forceinline__ float hlo(unsigned v) {
    __half2 h = *reinterpret_cast<__half2*>(&v);
    return __low2float(h);
}
static __device__ __forceinline__ float hhi(unsigned v) {
    __half2 h = *reinterpret_cast<__half2*>(&v);
    return __high2float(h);
}

// ---------- prep: fp16 hi/lo B khalf tiles (stride-144 rows) + W1T chunks ----------
__global__ void prep_kernel(const float* __restrict__ encW, const float* __restrict__ Wq,
                            const float* __restrict__ Wk,  const float* __restrict__ Wv,
                            const float* __restrict__ W1)
{
    int b = blockIdx.x;
    if (b < 7) {
        const float* src; int K;
        if (b == 0) { src = encW; K = 64; }
        else {
            int i = b - 1, l = i / 3, w = i % 3;
            src = (w == 0 ? Wq : w == 1 ? Wk : Wv) + l*16384; K = 128;
        }
        unsigned char* base = g_wpre + b*PROJ_B;
        int nkh = K / 64;
        for (int idx = threadIdx.x; idx < nkh*128*72; idx += blockDim.x) {
            int kh = idx / (128*72);
            int rem = idx % (128*72);
            int n = rem / 72, kk = rem % 72;
            float v = (kk < 64) ? src[(kh*64 + kk)*128 + n] : 0.f;
            __half h = __float2half(v);
            __half lo = __float2half(v - __half2float(h));
            unsigned char* d = base + kh*36864 + n*144 + kk*2;
            *(__half*)d           = h;
            *(__half*)(d + 18432) = lo;
        }
    } else {
        int c = b - 7;
        float* dst = (float*)(g_wpre + W1T_OFF + c*18432);
        for (int idx = threadIdx.x; idx < 128*36; idx += blockDim.x) {
            int col = idx / 36, kk = idx % 36;
            dst[col*36 + kk] = (kk < 32) ? W1[(c*32 + kk)*128 + col] : 0.f;
        }
    }
}

// one B-pass projection MMA for one khalf; 2 graphs x 32 cols per warp
static __device__ __forceinline__ void mma_pass(unsigned aB0, unsigned aB1, unsigned aoff,
                                                unsigned bBase, float* __restrict__ acc,
                                                int lane)
{
    const unsigned aLane = (unsigned)((lane & 15)*272 + (lane >> 4)*16);
    const int m = lane >> 3, r = lane & 7;
    const unsigned bLane = (unsigned)(((m >> 1)*8 + r)*144 + (m & 1)*16);
#pragma unroll
    for (int ks = 0; ks < 4; ks++) {
        unsigned a0[4], a1[4];
        LDSM4(a0[0],a0[1],a0[2],a0[3], aB0 + aoff + ks*32 + aLane);
        LDSM4(a1[0],a1[1],a1[2],a1[3], aB1 + aoff + ks*32 + aLane);
#pragma unroll
        for (int j = 0; j < 2; j++) {
            unsigned ab = bBase + (unsigned)(j*2304 + ks*32) + bLane;
            unsigned b0,b1,b2,b3;
            LDSM4(b0,b1,b2,b3, ab);
            float* p00 = acc + j*8;      float* p01 = acc + j*8 + 4;
            float* p10 = acc + 16 + j*8; float* p11 = acc + 16 + j*8 + 4;
            MMA4(p00, a0, b0, b1); MMA4(p01, a0, b2, b3);
            MMA4(p10, a1, b0, b1); MMA4(p11, a1, b2, b3);
        }
    }
}

static __device__ __forceinline__ void acc_init_g(float* acc, const float* __restrict__ bp,
                                                  int cq, int lane) {
    const int q2 = (lane & 3)*2;
#pragma unroll
    for (int nt = 0; nt < 4; nt++) {
        int col = 32*cq + nt*8 + q2;
        float2 bv2 = __ldg((const float2*)(bp + col));
        acc[nt*4]=bv2.x; acc[nt*4+1]=bv2.y; acc[nt*4+2]=bv2.x; acc[nt*4+3]=bv2.y;
        acc[16+nt*4]=bv2.x; acc[16+nt*4+1]=bv2.y;
        acc[16+nt*4+2]=bv2.x; acc[16+nt*4+3]=bv2.y;
    }
}

__global__ void __launch_bounds__(THREADS, 2)
gnn_mma_kernel(const float* __restrict__ x,
               const float* __restrict__ enc_b, const float* __restrict__ bq,
               const float* __restrict__ bk,    const float* __restrict__ bv,
               const float* __restrict__ ln_g,  const float* __restrict__ ln_b,
               const float* __restrict__ b1,    const float* __restrict__ W2,
               const float* __restrict__ b2,    float* __restrict__ out)
{
    extern __shared__ float sm[];
    char* smc = (char*)sm;
    const unsigned smb = su32(sm);
    float* bias = sm + BIAS_F;
    const int tid = threadIdx.x, lane = tid & 31, warp = tid >> 5;
    const int gs = warp >> 1, wsub = warp & 1, n0 = wsub * 8;
    const int cq = warp;                       // projection: warp = col quarter (= head!)
    const int gq = lane >> 2, q2 = (lane & 3)*2;

    if (tid == 0) {
        mbar_init(smb + MB0, 1); mbar_init(smb + MB1, 1);
        asm volatile("fence.proxy.async.shared::cta;" ::: "memory");
        bulk_issue(smb + BUF_HI, g_wpre,         18432u, smb + MB0);
        bulk_issue(smb + BUF_LO, g_wpre + 18432, 18432u, smb + MB1);
    }
    for (int i = tid; i < 256; i += THREADS) {
        bias[SB_LNG + i] = ln_g[i];
        bias[SB_LNB + i] = ln_b[i];
    }
    for (int i = tid; i < 128; i += THREADS) bias[SB_B1 + i] = b1[i];
    if (tid < NC) bias[SB_B2 + tid] = b2[tid];
    {   // stage x as fp16 A-mirror (2 graphs, K=64)
        const float4* xs = (const float4*)(x + (size_t)blockIdx.x * (G*16*64));
        for (int i = tid; i < 512; i += THREADS) {
            int g = i >> 8, row = (i >> 4) & 15, kq = i & 15;
            float4 t = xs[i];
            unsigned off = AB + (unsigned)((g*16 + row)*272 + kq*8);
            *(unsigned*)(smc + off)     = packh2(t.x, t.y);
            *(unsigned*)(smc + off + 4) = packh2(t.z, t.w);
        }
    }
    __syncthreads();

    const unsigned aB0 = smb + AB;
    const unsigned aB1 = smb + AB + 16*272;
    const unsigned bOfs = (unsigned)(cq*4608);
    float acc[32];

    // ---- encode (stage 0): h = x @ enc_W + enc_b -> A-mirror ----
    acc_init_g(acc, enc_b, cq, lane);
    mbw(smb + MB0, 0);
    mma_pass(aB0, aB1, 0, smb + BUF_HI + bOfs, acc, lane);
    __syncthreads();
    if (tid == 0) bulk_issue(smb + BUF_HI, g_wpre + PROJ_B, 18432u, smb + MB0);
    mbw(smb + MB1, 0);
    mma_pass(aB0, aB1, 0, smb + BUF_LO + bOfs, acc, lane);
    __syncthreads();
    if (tid == 0) bulk_issue(smb + BUF_LO, g_wpre + PROJ_B + 18432, 18432u, smb + MB1);
#pragma unroll
    for (int ga = 0; ga < 2; ga++) {
#pragma unroll
        for (int nt = 0; nt < 4; nt++) {
            int idx = ga*16 + nt*4;
            int lc  = 32*cq + nt*8 + q2;
            unsigned o0 = AB + (unsigned)((ga*16 + gq)*272 + lc*2);
            *(unsigned*)(smc + o0)           = packh2(acc[idx],   acc[idx+1]);
            *(unsigned*)(smc + o0 + 8*272)   = packh2(acc[idx+2], acc[idx+3]);
        }
    }
    __syncthreads();

    const float scale = 0.1767766952966369f;
    for (int l = 0; l < 2; l++) {
        for (int s = 0; s < 3; s++) {
            const float* bp = (s == 0 ? bq : s == 1 ? bk : bv) + 128*l;
            acc_init_g(acc, bp, cq, lane);
#pragma unroll
            for (int kh = 0; kh < 2; kh++) {
                int st = 1 + l*6 + s*2 + kh;
                int nx = st + 1;
                const unsigned char* nsrc = (nx <= 12)
                    ? g_wpre + (1 + (nx - 1)/2)*PROJ_B + ((nx - 1) & 1)*36864
                    : g_wpre + W1T_OFF;
                mbw(smb + MB0, st & 1);
                mma_pass(aB0, aB1, (unsigned)(kh*128), smb + BUF_HI + bOfs, acc, lane);
                __syncthreads();
                if (tid == 0) bulk_issue(smb + BUF_HI, nsrc, 18432u, smb + MB0);
                mbw(smb + MB1, st & 1);
                mma_pass(aB0, aB1, (unsigned)(kh*128), smb + BUF_LO + bOfs, acc, lane);
                __syncthreads();
                if (tid == 0) bulk_issue(smb + BUF_LO, nsrc + 18432, 18432u, smb + MB1);
            }
            // epilogue -> fp16 Q/K/V tile (16 x 272B rows per graph)
            unsigned qoff = QKV + (unsigned)(s*4352);
#pragma unroll
            for (int ga = 0; ga < 2; ga++) {
                unsigned base = qoff + (unsigned)(ga*13056);
#pragma unroll
                for (int nt = 0; nt < 4; nt++) {
                    int idx = ga*16 + nt*4;
                    int lc  = 32*cq + nt*8 + q2;
                    *(unsigned*)(smc + base + gq*272 + lc*2) =
                        packh2(acc[idx], acc[idx+1]);
                    *(unsigned*)(smc + base + (gq + 8)*272 + lc*2) =
                        packh2(acc[idx+2], acc[idx+3]);
                }
            }
        }
        __syncthreads();

        // ---- attention via tensor cores: warp = (graph, head pair) ----
        {
            const int hp = warp & 1;
            const unsigned qb = smb + QKV + (unsigned)((warp >> 1)*13056);
            const unsigned kb = qb + 4352;
            const unsigned vb = qb + 8704;
            const unsigned aL = (unsigned)((lane & 15)*272 + (lane >> 4)*16);
            const int m = lane >> 3, r = lane & 7;
            const unsigned bL = (unsigned)(((m >> 1)*8 + r)*272 + (m & 1)*16);
            const unsigned tL = (unsigned)(((m & 1)*8 + r)*272 + (m >> 1)*16);
            float* ost = sm + OSTF + (warp >> 1)*2304;
            const int g = lane >> 2;
#pragma unroll
            for (int hi = 0; hi < 2; hi++) {
                int h = 2*hp + hi;
                unsigned hb = (unsigned)(64*h);
                float sc[8];
#pragma unroll
                for (int i = 0; i < 8; i++) sc[i] = 0.f;
#pragma unroll
                for (int ks = 0; ks < 2; ks++) {
                    unsigned a[4], b[4];
                    LDSM4(a[0],a[1],a[2],a[3], qb + hb + ks*32 + aL);
                    LDSM4(b[0],b[1],b[2],b[3], kb + hb + ks*32 + bL);
                    MMA4(sc,     a, b[0], b[1]);
                    MMA4(sc + 4, a, b[2], b[3]);
                }
#pragma unroll
                for (int i = 0; i < 8; i++) sc[i] *= scale;
                // softmax along cols (16) ; rows g and g+8
                float mg = fmaxf(fmaxf(sc[0], sc[1]), fmaxf(sc[4], sc[5]));
                float mh = fmaxf(fmaxf(sc[2], sc[3]), fmaxf(sc[6], sc[7]));
                mg = fmaxf(mg, __shfl_xor_sync(0xffffffffu, mg, 1));
                mg = fmaxf(mg, __shfl_xor_sync(0xffffffffu, mg, 2));
                mh = fmaxf(mh, __shfl_xor_sync(0xffffffffu, mh, 1));
                mh = fmaxf(mh, __shfl_xor_sync(0xffffffffu, mh, 2));
                sc[0] = __expf(sc[0]-mg); sc[1] = __expf(sc[1]-mg);
                sc[4] = __expf(sc[4]-mg); sc[5] = __expf(sc[5]-mg);
                sc[2] = __expf(sc[2]-mh); sc[3] = __expf(sc[3]-mh);
                sc[6] = __expf(sc[6]-mh); sc[7] = __expf(sc[7]-mh);
                float sg = sc[0] + sc[1] + sc[4] + sc[5];
                float sh = sc[2] + sc[3] + sc[6] + sc[7];
                sg += __shfl_xor_sync(0xffffffffu, sg, 1);
                sg += __shfl_xor_sync(0xffffffffu, sg, 2);
                sh += __shfl_xor_sync(0xffffffffu, sh, 1);
                sh += __shfl_xor_sync(0xffffffffu, sh, 2);
                float ig = 1.f / sg, ih = 1.f / sh;
                unsigned pa[4];
                pa[0] = packh2(sc[0]*ig, sc[1]*ig);
                pa[1] = packh2(sc[2]*ih, sc[3]*ih);
                pa[2] = packh2(sc[4]*ig, sc[5]*ig);
                pa[3] = packh2(sc[6]*ih, sc[7]*ih);
                // O = P @ V  (V via ldmatrix trans)
                float ov[16];
#pragma unroll
                for (int i = 0; i < 16; i++) ov[i] = 0.f;
                unsigned v0[4], v1[4];
                LDSM4T(v0[0],v0[1],v0[2],v0[3], vb + hb + tL);
                LDSM4T(v1[0],v1[1],v1[2],v1[3], vb + hb + 32 + tL);
                MMA4(ov,      pa, v0[0], v0[1]);
                MMA4(ov + 4,  pa, v0[2], v0[3]);
                MMA4(ov + 8,  pa, v1[0], v1[1]);
                MMA4(ov + 12, pa, v1[2], v1[3]);
                // store O to fp32 staging (144-stride, head offset 36h)
#pragma unroll
                for (int nb = 0; nb < 4; nb++) {
                    int off = 36*h + 8*nb + q2;
                    *(float2*)(ost + g*144 + off)       = make_float2(ov[4*nb],   ov[4*nb+1]);
                    *(float2*)(ost + (g + 8)*144 + off) = make_float2(ov[4*nb+2], ov[4*nb+3]);
                }
            }
        }
        __syncthreads();

        // ---- residual(mirror) + LN (writes new mirror) ----
        {
            float* ost = sm + OSTF + gs*2304;
            const int n  = n0 + (lane & 7);
            const int hh = lane >> 3;
            const int co = hh * 36, ch = hh * 32;
            float o[32];
            const float* orow = ost + n*144 + co;
#pragma unroll
            for (int j = 0; j < 8; j++) {
                float4 t = *(const float4*)(orow + 4*j);
                o[4*j] = t.x; o[4*j+1] = t.y; o[4*j+2] = t.z; o[4*j+3] = t.w;
            }
            char* ap = smc + AB + (unsigned)((gs*16 + n)*272 + ch*2);
#pragma unroll
            for (int u = 0; u < 4; u++) {
                uint4 H = *(const uint4*)(ap + 16*u);
                o[8*u]   += hlo(H.x);  o[8*u+1] += hhi(H.x);
                o[8*u+2] += hlo(H.y);  o[8*u+3] += hhi(H.y);
                o[8*u+4] += hlo(H.z);  o[8*u+5] += hhi(H.z);
                o[8*u+6] += hlo(H.w);  o[8*u+7] += hhi(H.w);
            }
            float lsum = 0.f, lsq = 0.f;
#pragma unroll
            for (int j = 0; j < 32; j++) { lsum += o[j]; lsq += o[j]*o[j]; }
            lsum += __shfl_xor_sync(0xffffffffu, lsum, 8);
            lsq  += __shfl_xor_sync(0xffffffffu, lsq,  8);
            lsum += __shfl_xor_sync(0xffffffffu, lsum, 16);
            lsq  += __shfl_xor_sync(0xffffffffu, lsq,  16);
            float mean = lsum * (1.f/HID);
            float var  = lsq  * (1.f/HID) - mean*mean;
            float rstd = rsqrtf(var + 1e-5f);
#pragma unroll
            for (int j = 0; j < 32; j++)
                o[j] = (o[j] - mean)*rstd*bias[SB_LNG + 128*l + ch + j]
                       + bias[SB_LNB + 128*l + ch + j];
#pragma unroll
            for (int u = 0; u < 4; u++) {
                uint4 w4;
                w4.x = packh2(o[8*u],     o[8*u + 1]);
                w4.y = packh2(o[8*u + 2], o[8*u + 3]);
                w4.z = packh2(o[8*u + 4], o[8*u + 5]);
                w4.w = packh2(o[8*u + 6], o[8*u + 7]);
                *(uint4*)(ap + 16*u) = w4;
            }
        }
        __syncthreads();
    }

    {   // pooling from mirror -> scr (mean[0..127] | max[128..255]) per graph
        int cp = wsub*64 + 2*lane;
        const char* ap = smc + AB + (unsigned)((gs*16)*272 + cp*2);
        float s0 = 0.f, s1 = 0.f, m0 = -3.4e38f, m1 = -3.4e38f;
#pragma unroll
        for (int nn = 0; nn < 16; nn++) {
            unsigned H = *(const unsigned*)(ap + nn*272);
            float h0 = hlo(H), h1 = hhi(H);
            s0 += h0; m0 = fmaxf(m0, h0);
            s1 += h1; m1 = fmaxf(m1, h1);
        }
        float* scr = sm + OSTF + gs*2304;
        *(float2*)(scr + cp)       = make_float2(s0*(1.f/16.f), s1*(1.f/16.f));
        *(float2*)(scr + 128 + cp) = make_float2(m0, m1);
    }
    __syncthreads();

    // ---- MLP layer 1: W1T in 8 32-k chunks ping-ponged through hi/lo bufs ----
    int mb0u = 13, mb1u = 13;
    {
        int g2 = lane >> 4, c16 = lane & 15;
        int c = warp*32 + c16;
        float a1 = bias[SB_B1 + c], a2 = bias[SB_B1 + c + 16];
        const float* pooled = sm + OSTF + g2*2304;
        for (int ch = 0; ch < 8; ch++) {
            unsigned mb = (ch & 1) ? MB1 : MB0;
            int par = ((ch & 1) ? mb1u++ : mb0u++) & 1;
            mbw(smb + mb, par);
            const float* Wc = (const float*)(smc + ((ch & 1) ? BUF_LO : BUF_HI));
#pragma unroll
            for (int k4 = 0; k4 < 8; k4++) {
                float4 p = *(const float4*)(pooled + ch*32 + 4*k4);
                float4 w = *(const float4*)(Wc + c*36 + 4*k4);
                float4 v = *(const float4*)(Wc + (c + 16)*36 + 4*k4);
                a1 = fmaf(p.x, w.x, fmaf(p.y, w.y, fmaf(p.z, w.z, fmaf(p.w, w.w, a1))));
                a2 = fmaf(p.x, v.x, fmaf(p.y, v.y, fmaf(p.z, v.z, fmaf(p.w, v.w, a2))));
            }
            __syncthreads();
            if (tid == 0) {
                if (ch + 2 <= 7)
                    bulk_issue(smb + ((ch & 1) ? BUF_LO : BUF_HI),
                               g_wpre + W1T_OFF + (ch + 2)*18432, 18432u, smb + mb);
                else if (ch == 6)
                    bulk_issue(smb + BUF_HI, W2, 5120u, smb + MB0);
            }
        }
        float* hid = sm + OSTF + g2*2304 + 256;
        hid[c]      = fmaxf(a1, 0.f);
        hid[c + 16] = fmaxf(a2, 0.f);
    }
    __syncthreads();

    // ---- logits = hid @ W2 + b2 ----
    mbw(smb + MB0, mb0u & 1);                 // W2 = MB0 completion #17 -> parity 1
    {
        const float* Wc = (const float*)(smc + BUF_HI);
        if (wsub == 0 && lane < NC) {
            const float* hid = sm + OSTF + gs*2304 + 256;
            float a = bias[SB_B2 + lane];
#pragma unroll 8
            for (int k = 0; k < HID; k++)
                a = fmaf(hid[k], Wc[k*NC + lane], a);
            out[((size_t)blockIdx.x*G + gs)*NC + lane] = a;
        }
    }
}

extern "C" void kernel_launch(void* const* d_in, const int* in_sizes, int n_in,
                              void* d_out, int out_size)
{
    const float* x     = (const float*)d_in[0];
    const float* enc_W = (const float*)d_in[1];
    const float* enc_b = (const float*)d_in[2];
    const float* Wq    = (const float*)d_in[3];
    const float* bq    = (const float*)d_in[4];
    const float* Wk    = (const float*)d_in[5];
    const float* bk    = (const float*)d_in[6];
    const float* Wv    = (const float*)d_in[7];
    const float* bv    = (const float*)d_in[8];
    const float* ln_g  = (const float*)d_in[9];
    const float* ln_b  = (const float*)d_in[10];
    const float* W1    = (const float*)d_in[11];
    const float* b1    = (const float*)d_in[12];
    const float* W2    = (const float*)d_in[13];
    const float* b2    = (const float*)d_in[14];
    float* out = (float*)d_out;

    prep_kernel<<<15, 256>>>(enc_W, Wq, Wk, Wv, W1);
    cudaFuncSetAttribute(gnn_mma_kernel,
                         cudaFuncAttributeMaxDynamicSharedMemorySize, SMEM_BYTES);
    gnn_mma_kernel<<<B_TOTAL / G, THREADS, SMEM_BYTES>>>(
        x, enc_b, bq, bk, bv, ln_g, ln_b, b1, W2, b2, out);
}